// round 11
// baseline (speedup 1.0000x reference)
#include <cuda_runtime.h>
#include <cuda_bf16.h>
#include <stdint.h>
#include <math.h>

#define N_NODES_MAX 16384
#define IN_DIM 512
#define MEM_DIM 256
#define VOCAB 64
#define MAX_CH 8

// Scratch (allocation-free rule: __device__ globals)
__device__ float g_X[N_NODES_MAX * MEM_DIM];            // inputs @ W_in^T + b
__device__ float g_P[N_NODES_MAX * MEM_DIM];            // states @ W_ch^T
__device__ float g_D[VOCAB * MEM_DIM];                  // deprel_emb @ W_dep^T
__device__ __nv_bfloat16 g_Wh[MEM_DIM * 1024];          // W split hi
__device__ __nv_bfloat16 g_Wl[MEM_DIM * 1024];          // W split lo
__device__ __nv_bfloat16 g_Sh[N_NODES_MAX * MEM_DIM];   // states split hi
__device__ __nv_bfloat16 g_Sl[N_NODES_MAX * MEM_DIM];   // states split lo
__device__ __nv_bfloat16 g_Ih[N_NODES_MAX * IN_DIM];    // inputs split hi
__device__ __nv_bfloat16 g_Il[N_NODES_MAX * IN_DIM];    // inputs split lo
__device__ __nv_bfloat16 g_Eh[VOCAB * MEM_DIM];         // deprel split hi
__device__ __nv_bfloat16 g_El[VOCAB * MEM_DIM];         // deprel split lo

#define AROW 24   // bf16 elems per smem row: 16 data + 8 pad (48B, 16B-aligned)

__device__ __forceinline__ void ldsm4(unsigned& r0, unsigned& r1,
                                      unsigned& r2, unsigned& r3, unsigned addr) {
    asm volatile("ldmatrix.sync.aligned.m8n8.x4.shared.b16 {%0,%1,%2,%3}, [%4];"
                 : "=r"(r0), "=r"(r1), "=r"(r2), "=r"(r3) : "r"(addr));
}

__device__ __forceinline__ void mma16816(float* c,
                                         unsigned a0, unsigned a1, unsigned a2, unsigned a3,
                                         unsigned b0, unsigned b1) {
    asm volatile(
        "mma.sync.aligned.m16n8k16.row.col.f32.bf16.bf16.f32 "
        "{%0,%1,%2,%3}, {%4,%5,%6,%7}, {%8,%9}, {%0,%1,%2,%3};"
        : "+f"(c[0]), "+f"(c[1]), "+f"(c[2]), "+f"(c[3])
        : "r"(a0), "r"(a1), "r"(a2), "r"(a3), "r"(b0), "r"(b1));
}

__device__ __forceinline__ void cp16(unsigned saddr, const void* gptr, unsigned src_bytes) {
    asm volatile("cp.async.cg.shared.global [%0], [%1], 16, %2;"
                 :: "r"(saddr), "l"(gptr), "r"(src_bytes));
}
__device__ __forceinline__ void cp_commit() {
    asm volatile("cp.async.commit_group;");
}
template<int N>
__device__ __forceinline__ void cp_wait() {
    asm volatile("cp.async.wait_group %0;" :: "n"(N));
}

__device__ __forceinline__ void split2(float x, float y,
                                       __nv_bfloat162& hi, __nv_bfloat162& lo) {
    __nv_bfloat16 hx = __float2bfloat16(x);
    __nv_bfloat16 hy = __float2bfloat16(y);
    hi = __halves2bfloat162(hx, hy);
    lo = __halves2bfloat162(__float2bfloat16(x - __bfloat162float(hx)),
                            __float2bfloat16(y - __bfloat162float(hy)));
}

// generic fp32 -> bf16 hi/lo split, 4 elems per thread
__global__ __launch_bounds__(256)
void split_f32(const float* __restrict__ src,
               __nv_bfloat16* __restrict__ h, __nv_bfloat16* __restrict__ l, int n4) {
    int i = blockIdx.x * 256 + threadIdx.x;
    if (i >= n4) return;
    float4 v = *(const float4*)(src + (long)i * 4);
    __nv_bfloat162 a, b;
    split2(v.x, v.y, a, b);
    ((__nv_bfloat162*)(h + (long)i * 4))[0] = a;
    ((__nv_bfloat162*)(l + (long)i * 4))[0] = b;
    split2(v.z, v.w, a, b);
    ((__nv_bfloat162*)(h + (long)i * 4))[1] = a;
    ((__nv_bfloat162*)(l + (long)i * 4))[1] = b;
}

// ---------------------------------------------------------------------------
// C[m,n] = sum_k A[m,k] * W[n, wofs+k] (+ bias[n]); A,W pre-split bf16 hi/lo.
// 3-pass split-bf16 tensor GEMM: C ~= Ah*Wh + Ah*Wl + Al*Wh, fp32 accum.
// Block 64(M) x 128(N), BK=16, 2-stage cp.async pipeline, 8 warps (2M x 4N),
// warp tile 32x32. LEAF_TANH: rows >= first_leaf -> tanh to S + split Sh/Sl.
// ---------------------------------------------------------------------------
template<bool HAS_BIAS, bool LEAF_TANH>
__global__ __launch_bounds__(256)
void rcnn_gemm_mma(const __nv_bfloat16* __restrict__ Agh,
                   const __nv_bfloat16* __restrict__ Agl, int lda,
                   const __nv_bfloat16* __restrict__ Wh,
                   const __nv_bfloat16* __restrict__ Wl, int wofs,
                   const float* __restrict__ bias,
                   float* __restrict__ Cmat, int M, int K,
                   float* __restrict__ S,
                   __nv_bfloat16* __restrict__ Sh,
                   __nv_bfloat16* __restrict__ Sl, int first_leaf) {
    __shared__ __nv_bfloat16 sAh[2][64 * AROW];
    __shared__ __nv_bfloat16 sAl[2][64 * AROW];
    __shared__ __nv_bfloat16 sBh[2][128 * AROW];
    __shared__ __nv_bfloat16 sBl[2][128 * AROW];

    const int tid  = threadIdx.x;
    const int lane = tid & 31;
    const int warp = tid >> 5;
    const int wm   = warp >> 2;          // 0..1 : 32 M-rows
    const int wn   = warp & 3;           // 0..3 : 32 N-cols
    const int bm   = blockIdx.x * 64;
    const int bn   = blockIdx.y * 128;

    // cp.async loader mapping
    const int a_r = (tid & 127) >> 1;    // 0..63
    const int a_c = (tid & 1) * 8;       // 0 or 8 (chunk of 8 bf16 = 16B)
    const bool a_lo = (tid >= 128);      // low half loads Agh, high half Agl
    const int b_r = tid >> 1;            // 0..127
    const int b_c = (tid & 1) * 8;

    // clamped A row address (src_bytes=0 masks OOB reads)
    const int a_gr = bm + a_r;
    const unsigned a_sz = (a_gr < M) ? 16u : 0u;
    const long a_base = (long)((a_gr < M) ? a_gr : (M - 1)) * lda;
    const __nv_bfloat16* Asrc = a_lo ? Agl : Agh;
    __nv_bfloat16* Adst0 = a_lo ? sAl[0] : sAh[0];
    __nv_bfloat16* Adst1 = a_lo ? sAl[1] : sAh[1];
    const long b_base = (long)(bn + b_r) * 1024 + wofs;

    unsigned sa0 = (unsigned)__cvta_generic_to_shared(Adst0 + a_r * AROW + a_c);
    unsigned sa1 = (unsigned)__cvta_generic_to_shared(Adst1 + a_r * AROW + a_c);
    unsigned sbh0 = (unsigned)__cvta_generic_to_shared(sBh[0] + b_r * AROW + b_c);
    unsigned sbh1 = (unsigned)__cvta_generic_to_shared(sBh[1] + b_r * AROW + b_c);
    unsigned sbl0 = (unsigned)__cvta_generic_to_shared(sBl[0] + b_r * AROW + b_c);
    unsigned sbl1 = (unsigned)__cvta_generic_to_shared(sBl[1] + b_r * AROW + b_c);

    // issue stage into buffer buf covering k-offset kof
    auto issue = [&](int buf, int kof) {
        cp16(buf ? sa1 : sa0, Asrc + a_base + kof + a_c, a_sz);
        cp16(buf ? sbh1 : sbh0, Wh + b_base + kof + b_c, 16u);
        cp16(buf ? sbl1 : sbl0, Wl + b_base + kof + b_c, 16u);
        cp_commit();
    };

    float acc[2][4][4];
    #pragma unroll
    for (int i = 0; i < 2; ++i) {
        #pragma unroll
        for (int j = 0; j < 4; ++j) {
            #pragma unroll
            for (int q = 0; q < 4; ++q) { acc[i][j][q] = 0.f; }
        }
    }

    issue(0, 0);
    if (K > 16) issue(1, 16);

    // ldmatrix per-thread coordinates
    const int gq8 = lane >> 3;
    const int wi  = lane & 7;
    const int a_row = wm * 32 + wi + 8 * (gq8 & 1);   // + mt*16
    const int a_kh  = (gq8 >> 1) * 8;
    const int b_row = wn * 32 + wi + 8 * (gq8 >> 1);  // + p*16
    const int b_kh  = (gq8 & 1) * 8;

    int cur = 0;
    for (int k0 = 0; k0 < K; k0 += 16) {
        if (k0 + 16 < K) { cp_wait<1>(); } else { cp_wait<0>(); }
        __syncthreads();

        // fragments
        unsigned Ahf[2][4], Alf[2][4], Bhf[2][4], Blf[2][4];
        #pragma unroll
        for (int mt = 0; mt < 2; ++mt) {
            unsigned off = (unsigned)((a_row + mt * 16) * AROW + a_kh) * 2u;
            unsigned ah = (unsigned)__cvta_generic_to_shared(sAh[cur]) + off;
            unsigned al = (unsigned)__cvta_generic_to_shared(sAl[cur]) + off;
            ldsm4(Ahf[mt][0], Ahf[mt][1], Ahf[mt][2], Ahf[mt][3], ah);
            ldsm4(Alf[mt][0], Alf[mt][1], Alf[mt][2], Alf[mt][3], al);
        }
        #pragma unroll
        for (int p = 0; p < 2; ++p) {
            unsigned off = (unsigned)((b_row + p * 16) * AROW + b_kh) * 2u;
            unsigned bh = (unsigned)__cvta_generic_to_shared(sBh[cur]) + off;
            unsigned bl = (unsigned)__cvta_generic_to_shared(sBl[cur]) + off;
            ldsm4(Bhf[p][0], Bhf[p][1], Bhf[p][2], Bhf[p][3], bh);
            ldsm4(Blf[p][0], Blf[p][1], Blf[p][2], Blf[p][3], bl);
        }

        // 3-pass MMA: hi*hi + hi*lo + lo*hi
        #pragma unroll
        for (int mt = 0; mt < 2; ++mt) {
            #pragma unroll
            for (int p = 0; p < 2; ++p) {
                #pragma unroll
                for (int nh = 0; nh < 2; ++nh) {
                    float* c = acc[mt][p * 2 + nh];
                    mma16816(c, Ahf[mt][0], Ahf[mt][1], Ahf[mt][2], Ahf[mt][3],
                             Bhf[p][2 * nh], Bhf[p][2 * nh + 1]);
                    mma16816(c, Ahf[mt][0], Ahf[mt][1], Ahf[mt][2], Ahf[mt][3],
                             Blf[p][2 * nh], Blf[p][2 * nh + 1]);
                    mma16816(c, Alf[mt][0], Alf[mt][1], Alf[mt][2], Alf[mt][3],
                             Bhf[p][2 * nh], Bhf[p][2 * nh + 1]);
                }
            }
        }

        if (k0 + 32 < K) {
            __syncthreads();          // everyone done reading cur
            issue(cur, k0 + 32);      // refill cur for k0+32
        }
        cur ^= 1;
    }

    // epilogue
    const int gq  = lane >> 2;
    const int tig = lane & 3;
    #pragma unroll
    for (int mt = 0; mt < 2; ++mt) {
        #pragma unroll
        for (int rh = 0; rh < 2; ++rh) {
            const int row = bm + wm * 32 + mt * 16 + rh * 8 + gq;
            if (row >= M) continue;
            const bool leaf = LEAF_TANH && (row >= first_leaf);
            #pragma unroll
            for (int nt = 0; nt < 4; ++nt) {
                const int col = bn + wn * 32 + nt * 8 + 2 * tig;
                float v0 = acc[mt][nt][2 * rh + 0];
                float v1 = acc[mt][nt][2 * rh + 1];
                if (HAS_BIAS) { v0 += bias[col]; v1 += bias[col + 1]; }
                if (leaf) {
                    v0 = tanhf(v0); v1 = tanhf(v1);
                    *(float2*)(S + (long)row * MEM_DIM + col) = make_float2(v0, v1);
                    __nv_bfloat162 h, l;
                    split2(v0, v1, h, l);
                    *(__nv_bfloat162*)(Sh + (long)row * MEM_DIM + col) = h;
                    *(__nv_bfloat162*)(Sl + (long)row * MEM_DIM + col) = l;
                } else {
                    *(float2*)(Cmat + (long)row * MEM_DIM + col) = make_float2(v0, v1);
                }
            }
        }
    }
}

// ---------------------------------------------------------------------------
// Combine (warp-per-child for C==8; generic fallback). Writes fp32 states and
// bf16 split copies (A operand for upper-level P-GEMMs).
// ---------------------------------------------------------------------------
__global__ __launch_bounds__(256)
void rcnn_combine(int lo,
                  const int*   __restrict__ cidx,
                  const int*   __restrict__ cdep,
                  const int*   __restrict__ counts,
                  const float* __restrict__ X,
                  const float* __restrict__ D,
                  const float* __restrict__ P,
                  float*       __restrict__ S,
                  __nv_bfloat16* __restrict__ Sh,
                  __nv_bfloat16* __restrict__ Sl) {
    const int i   = lo + (int)blockIdx.x;
    const int tid = threadIdx.x;
    const int cnt = counts[i];

    __shared__ float r[MAX_CH * MEM_DIM];

    if (cnt == 8) {
        const int w = tid >> 5;
        const int l = tid & 31;
        const int g = l * 8;

        const int c  = cidx[i * MAX_CH + w];
        const int dv = cdep[i * MAX_CH + w];

        const float4 x0 = *(const float4*)(X + (long)i  * MEM_DIM + g);
        const float4 x1 = *(const float4*)(X + (long)i  * MEM_DIM + g + 4);
        const float4 d0 = *(const float4*)(D + (long)dv * MEM_DIM + g);
        const float4 d1 = *(const float4*)(D + (long)dv * MEM_DIM + g + 4);
        const float4 p0 = *(const float4*)(P + (long)c  * MEM_DIM + g);
        const float4 p1 = *(const float4*)(P + (long)c  * MEM_DIM + g + 4);

        float m = tanhf(x0.x + d0.x + p0.x);
        m = fmaxf(m, tanhf(x0.y + d0.y + p0.y));
        m = fmaxf(m, tanhf(x0.z + d0.z + p0.z));
        m = fmaxf(m, tanhf(x0.w + d0.w + p0.w));
        m = fmaxf(m, tanhf(x1.x + d1.x + p1.x));
        m = fmaxf(m, tanhf(x1.y + d1.y + p1.y));
        m = fmaxf(m, tanhf(x1.z + d1.z + p1.z));
        m = fmaxf(m, tanhf(x1.w + d1.w + p1.w));

        const long o = (long)i * MEM_DIM + w * 32 + l;
        S[o] = m;
        __nv_bfloat16 h = __float2bfloat16(m);
        Sh[o] = h;
        Sl[o] = __float2bfloat16(m - __bfloat162float(h));
        return;
    }

    // generic path (rare: C != 8, e.g. node 2047 with C=7)
    const int f = tid;
    const float x = X[(long)i * MEM_DIM + f];
    const long o = (long)i * MEM_DIM + f;

    if (cnt == 0) {
        float v = tanhf(x);
        S[o] = v;
        __nv_bfloat16 h = __float2bfloat16(v);
        Sh[o] = h;
        Sl[o] = __float2bfloat16(v - __bfloat162float(h));
        return;
    }
    const int C = cnt;

    for (int k = 0; k < C; ++k) {
        int c  = cidx[i * MAX_CH + k];
        int dv = cdep[i * MAX_CH + k];
        r[k * MEM_DIM + f] = tanhf(x + D[dv * MEM_DIM + f] + P[(long)c * MEM_DIM + f]);
    }
    __syncthreads();

    float mx = -3.402823466e38f;
    for (int t = 0; t < C; ++t) {
        int j = f * C + t;
        mx = fmaxf(mx, r[(j >> 8) * MEM_DIM + (j & 255)]);
    }
    S[o] = mx;
    __nv_bfloat16 h = __float2bfloat16(mx);
    Sh[o] = h;
    Sl[o] = __float2bfloat16(mx - __bfloat162float(h));
}

// ---------------------------------------------------------------------------
extern "C" void kernel_launch(void* const* d_in, const int* in_sizes, int n_in,
                              void* d_out, int out_size) {
    const float* inputs    = (const float*)d_in[0];   // [N, 512]
    const float* W         = (const float*)d_in[1];   // [256, 1024]
    const float* bvec      = (const float*)d_in[2];   // [256]
    const float* deprel    = (const float*)d_in[3];   // [64, 256]
    const int*   child_idx = (const int*)  d_in[4];   // [N, 8]
    const int*   child_dep = (const int*)  d_in[5];   // [N, 8]
    const int*   counts    = (const int*)  d_in[6];   // [N]
    float*       states    = (float*)d_out;           // [N, 256]

    float *X = 0, *P = 0, *D = 0;
    __nv_bfloat16 *Wh = 0, *Wl = 0, *Sh = 0, *Sl = 0, *Ih = 0, *Il = 0, *Eh = 0, *El = 0;
    cudaGetSymbolAddress((void**)&X,  g_X);
    cudaGetSymbolAddress((void**)&P,  g_P);
    cudaGetSymbolAddress((void**)&D,  g_D);
    cudaGetSymbolAddress((void**)&Wh, g_Wh);
    cudaGetSymbolAddress((void**)&Wl, g_Wl);
    cudaGetSymbolAddress((void**)&Sh, g_Sh);
    cudaGetSymbolAddress((void**)&Sl, g_Sl);
    cudaGetSymbolAddress((void**)&Ih, g_Ih);
    cudaGetSymbolAddress((void**)&Il, g_Il);
    cudaGetSymbolAddress((void**)&Eh, g_Eh);
    cudaGetSymbolAddress((void**)&El, g_El);

    const int N = in_sizes[0] / IN_DIM;               // 16384
    const int first_leaf = (N + MAX_CH - 2) / MAX_CH; // 2048

    // Phase -1: split all fp32 operands into bf16 hi/lo once.
    split_f32<<<(MEM_DIM * 1024 / 4 + 255) / 256, 256>>>(W, Wh, Wl, MEM_DIM * 1024 / 4);
    split_f32<<<((N * IN_DIM / 4) + 255) / 256, 256>>>(inputs, Ih, Il, N * IN_DIM / 4);
    split_f32<<<(VOCAB * MEM_DIM / 4 + 255) / 256, 256>>>(deprel, Eh, El, VOCAB * MEM_DIM / 4);

    // Phase 0: input projection + bias; leaf rows tanh'd + split in epilogue.
    rcnn_gemm_mma<true, true><<<dim3((unsigned)((N + 63) / 64), 2), 256>>>(
        Ih, Il, IN_DIM, Wh, Wl, 0, bvec, X, N, IN_DIM, states, Sh, Sl, first_leaf);
    // deprel projection (tiny)
    rcnn_gemm_mma<false, false><<<dim3(1, 2), 256>>>(
        Eh, El, MEM_DIM, Wh, Wl, IN_DIM, 0, D, VOCAB, MEM_DIM, 0, 0, 0, 0);

    // Level starts: s[L] = (8^L - 1)/7
    long s[12];
    s[0] = 0;
    int nl = 0;
    while (s[nl] < N) { s[nl + 1] = 8 * s[nl] + 1; nl++; }

    // Internal levels, bottom-up
    for (int L = nl - 1; L >= 0; --L) {
        long lo = s[L];
        long hi = s[L + 1] - 1;
        if (hi > first_leaf - 1) hi = first_leaf - 1;
        if (lo > hi) continue;

        long clo = 8 * lo + 1;
        long chi = 8 * hi + 8;
        if (chi > N - 1) chi = N - 1;
        int Mc = (int)(chi - clo + 1);

        // P[j] = states[j] @ W_ch^T, A read pre-split from Sh/Sl
        rcnn_gemm_mma<false, false><<<dim3((unsigned)((Mc + 63) / 64), 2), 256>>>(
            Sh + clo * MEM_DIM, Sl + clo * MEM_DIM, MEM_DIM,
            Wh, Wl, IN_DIM + MEM_DIM, 0, P + clo * MEM_DIM, Mc, MEM_DIM, 0, 0, 0, 0);

        rcnn_combine<<<(unsigned)(hi - lo + 1), 256>>>(
            (int)lo, child_idx, child_dep, counts, X, D, P, states, Sh, Sl);
    }
}

// round 12
// speedup vs baseline: 1.0769x; 1.0769x over previous
#include <cuda_runtime.h>
#include <cuda_bf16.h>
#include <stdint.h>
#include <math.h>

#define N_NODES_MAX 16384
#define IN_DIM 512
#define MEM_DIM 256
#define VOCAB 64
#define MAX_CH 8

// Scratch (allocation-free rule: __device__ globals)
__device__ float g_X[N_NODES_MAX * MEM_DIM];
__device__ float g_P[N_NODES_MAX * MEM_DIM];
__device__ float g_D[VOCAB * MEM_DIM];
__device__ __nv_bfloat16 g_Wh[MEM_DIM * 1024];
__device__ __nv_bfloat16 g_Wl[MEM_DIM * 1024];
__device__ __nv_bfloat16 g_Sh[N_NODES_MAX * MEM_DIM];
__device__ __nv_bfloat16 g_Sl[N_NODES_MAX * MEM_DIM];
__device__ __nv_bfloat16 g_Ih[N_NODES_MAX * IN_DIM];
__device__ __nv_bfloat16 g_Il[N_NODES_MAX * IN_DIM];
__device__ __nv_bfloat16 g_Eh[VOCAB * MEM_DIM];
__device__ __nv_bfloat16 g_El[VOCAB * MEM_DIM];

#define AROW 24              // bf16 per smem row: 16 data + 8 pad (48B)
#define NSTAGE 4
// per-stage byte offsets inside one stage block
#define ST_AH 0
#define ST_AL 3072           // 64*24*2
#define ST_BH 6144
#define ST_BL 12288          // ST_BH + 128*24*2/... (128*24*2 = 6144)
#define ST_BYTES 18432       // 6144 + 12288

__device__ __forceinline__ void ldsm4(unsigned& r0, unsigned& r1,
                                      unsigned& r2, unsigned& r3, unsigned addr) {
    asm volatile("ldmatrix.sync.aligned.m8n8.x4.shared.b16 {%0,%1,%2,%3}, [%4];"
                 : "=r"(r0), "=r"(r1), "=r"(r2), "=r"(r3) : "r"(addr));
}

__device__ __forceinline__ void mma16816(float* c,
                                         unsigned a0, unsigned a1, unsigned a2, unsigned a3,
                                         unsigned b0, unsigned b1) {
    asm volatile(
        "mma.sync.aligned.m16n8k16.row.col.f32.bf16.bf16.f32 "
        "{%0,%1,%2,%3}, {%4,%5,%6,%7}, {%8,%9}, {%0,%1,%2,%3};"
        : "+f"(c[0]), "+f"(c[1]), "+f"(c[2]), "+f"(c[3])
        : "r"(a0), "r"(a1), "r"(a2), "r"(a3), "r"(b0), "r"(b1));
}

__device__ __forceinline__ void cp16(unsigned saddr, const void* gptr, unsigned src_bytes) {
    asm volatile("cp.async.cg.shared.global [%0], [%1], 16, %2;"
                 :: "r"(saddr), "l"(gptr), "r"(src_bytes));
}
__device__ __forceinline__ void cp_commit() {
    asm volatile("cp.async.commit_group;");
}
template<int N>
__device__ __forceinline__ void cp_wait() {
    asm volatile("cp.async.wait_group %0;" :: "n"(N));
}

__device__ __forceinline__ void split2(float x, float y,
                                       __nv_bfloat162& hi, __nv_bfloat162& lo) {
    __nv_bfloat16 hx = __float2bfloat16(x);
    __nv_bfloat16 hy = __float2bfloat16(y);
    hi = __halves2bfloat162(hx, hy);
    lo = __halves2bfloat162(__float2bfloat16(x - __bfloat162float(hx)),
                            __float2bfloat16(y - __bfloat162float(hy)));
}

// generic fp32 -> bf16 hi/lo split, 4 elems per thread
__global__ __launch_bounds__(256)
void split_f32(const float* __restrict__ src,
               __nv_bfloat16* __restrict__ h, __nv_bfloat16* __restrict__ l, int n4) {
    int i = blockIdx.x * 256 + threadIdx.x;
    if (i >= n4) return;
    float4 v = *(const float4*)(src + (long)i * 4);
    __nv_bfloat162 a, b;
    split2(v.x, v.y, a, b);
    ((__nv_bfloat162*)(h + (long)i * 4))[0] = a;
    ((__nv_bfloat162*)(l + (long)i * 4))[0] = b;
    split2(v.z, v.w, a, b);
    ((__nv_bfloat162*)(h + (long)i * 4))[1] = a;
    ((__nv_bfloat162*)(l + (long)i * 4))[1] = b;
}

// ---------------------------------------------------------------------------
// C[m,n] = sum_k A[m,k] * W[n, wofs+k] (+ bias[n]); A,W pre-split bf16 hi/lo.
// 3-pass split-bf16 tensor GEMM, 4-stage cp.async pipeline, ONE sync/iter.
// Block 64(M) x 128(N), BK=16, 8 warps (2M x 4N), warp tile 32x32.
// ---------------------------------------------------------------------------
template<bool HAS_BIAS, bool LEAF_TANH>
__global__ __launch_bounds__(256)
void rcnn_gemm_mma(const __nv_bfloat16* __restrict__ Agh,
                   const __nv_bfloat16* __restrict__ Agl, int lda,
                   const __nv_bfloat16* __restrict__ Wh,
                   const __nv_bfloat16* __restrict__ Wl, int wofs,
                   const float* __restrict__ bias,
                   float* __restrict__ Cmat, int M, int K,
                   float* __restrict__ S,
                   __nv_bfloat16* __restrict__ Sh,
                   __nv_bfloat16* __restrict__ Sl, int first_leaf) {
    extern __shared__ char smem[];

    const int tid  = threadIdx.x;
    const int lane = tid & 31;
    const int warp = tid >> 5;
    const int wm   = warp >> 2;          // 0..1 : 32 M-rows
    const int wn   = warp & 3;           // 0..3 : 32 N-cols
    const int bm   = blockIdx.x * 64;
    const int bn   = blockIdx.y * 128;

    // cp.async loader mapping (3 cp16 per thread per stage)
    const int a_r = (tid & 127) >> 1;
    const int a_c = (tid & 1) * 8;
    const bool a_lo = (tid >= 128);
    const int b_r = tid >> 1;
    const int b_c = (tid & 1) * 8;

    const int a_gr = bm + a_r;
    const unsigned a_sz = (a_gr < M) ? 16u : 0u;
    const long a_base = (long)((a_gr < M) ? a_gr : (M - 1)) * lda;
    const __nv_bfloat16* Asrc = a_lo ? Agl : Agh;
    const long b_base = (long)(bn + b_r) * 1024 + wofs;

    // per-stage smem shared addresses for this thread's cp.async targets
    unsigned smem_u = (unsigned)__cvta_generic_to_shared(smem);
    unsigned sa_t[NSTAGE], sbh_t[NSTAGE], sbl_t[NSTAGE];
    #pragma unroll
    for (int s = 0; s < NSTAGE; ++s) {
        unsigned base = smem_u + s * ST_BYTES;
        sa_t[s]  = base + (a_lo ? ST_AL : ST_AH) + (unsigned)(a_r * AROW + a_c) * 2u;
        sbh_t[s] = base + ST_BH + (unsigned)(b_r * AROW + b_c) * 2u;
        sbl_t[s] = base + ST_BL + (unsigned)(b_r * AROW + b_c) * 2u;
    }

    const int ntile = K >> 4;

    // issue cp16s for tile t into stage t % NSTAGE (no commit here)
    auto issue = [&](int t) {
        const int s = t & (NSTAGE - 1);
        const int kof = t * 16;
        cp16(sa_t[s],  Asrc + a_base + kof + a_c, a_sz);
        cp16(sbh_t[s], Wh + b_base + kof + b_c, 16u);
        cp16(sbl_t[s], Wl + b_base + kof + b_c, 16u);
    };

    float acc[2][4][4];
    #pragma unroll
    for (int i = 0; i < 2; ++i) {
        #pragma unroll
        for (int j = 0; j < 4; ++j) {
            #pragma unroll
            for (int q = 0; q < 4; ++q) { acc[i][j][q] = 0.f; }
        }
    }

    // prologue: stages for tiles 0..2 (always 3 committed groups)
    #pragma unroll
    for (int s = 0; s < NSTAGE - 1; ++s) {
        if (s < ntile) issue(s);
        cp_commit();
    }

    // ldmatrix per-thread coordinates
    const int gq8 = lane >> 3;
    const int wi  = lane & 7;
    const int a_row = wm * 32 + wi + 8 * (gq8 & 1);
    const int a_kh  = (gq8 >> 1) * 8;
    const int b_row = wn * 32 + wi + 8 * (gq8 >> 1);
    const int b_kh  = (gq8 & 1) * 8;

    for (int it = 0; it < ntile; ++it) {
        cp_wait<NSTAGE - 2>();
        __syncthreads();

        // refill stage consumed at iter it-1 with tile it+3; always commit
        if (it + NSTAGE - 1 < ntile) issue(it + NSTAGE - 1);
        cp_commit();

        const unsigned sbase = smem_u + (unsigned)(it & (NSTAGE - 1)) * ST_BYTES;

        unsigned Ahf[2][4], Alf[2][4], Bhf[2][4], Blf[2][4];
        #pragma unroll
        for (int mt = 0; mt < 2; ++mt) {
            unsigned off = (unsigned)((a_row + mt * 16) * AROW + a_kh) * 2u;
            ldsm4(Ahf[mt][0], Ahf[mt][1], Ahf[mt][2], Ahf[mt][3], sbase + ST_AH + off);
            ldsm4(Alf[mt][0], Alf[mt][1], Alf[mt][2], Alf[mt][3], sbase + ST_AL + off);
        }
        #pragma unroll
        for (int p = 0; p < 2; ++p) {
            unsigned off = (unsigned)((b_row + p * 16) * AROW + b_kh) * 2u;
            ldsm4(Bhf[p][0], Bhf[p][1], Bhf[p][2], Bhf[p][3], sbase + ST_BH + off);
            ldsm4(Blf[p][0], Blf[p][1], Blf[p][2], Blf[p][3], sbase + ST_BL + off);
        }

        // 3-pass MMA: hi*hi + hi*lo + lo*hi
        #pragma unroll
        for (int mt = 0; mt < 2; ++mt) {
            #pragma unroll
            for (int p = 0; p < 2; ++p) {
                #pragma unroll
                for (int nh = 0; nh < 2; ++nh) {
                    float* c = acc[mt][p * 2 + nh];
                    mma16816(c, Ahf[mt][0], Ahf[mt][1], Ahf[mt][2], Ahf[mt][3],
                             Bhf[p][2 * nh], Bhf[p][2 * nh + 1]);
                    mma16816(c, Ahf[mt][0], Ahf[mt][1], Ahf[mt][2], Ahf[mt][3],
                             Blf[p][2 * nh], Blf[p][2 * nh + 1]);
                    mma16816(c, Alf[mt][0], Alf[mt][1], Alf[mt][2], Alf[mt][3],
                             Bhf[p][2 * nh], Bhf[p][2 * nh + 1]);
                }
            }
        }
    }

    // epilogue
    const int gq  = lane >> 2;
    const int tig = lane & 3;
    #pragma unroll
    for (int mt = 0; mt < 2; ++mt) {
        #pragma unroll
        for (int rh = 0; rh < 2; ++rh) {
            const int row = bm + wm * 32 + mt * 16 + rh * 8 + gq;
            if (row >= M) continue;
            const bool leaf = LEAF_TANH && (row >= first_leaf);
            #pragma unroll
            for (int nt = 0; nt < 4; ++nt) {
                const int col = bn + wn * 32 + nt * 8 + 2 * tig;
                float v0 = acc[mt][nt][2 * rh + 0];
                float v1 = acc[mt][nt][2 * rh + 1];
                if (HAS_BIAS) { v0 += bias[col]; v1 += bias[col + 1]; }
                if (leaf) {
                    v0 = tanhf(v0); v1 = tanhf(v1);
                    *(float2*)(S + (long)row * MEM_DIM + col) = make_float2(v0, v1);
                    __nv_bfloat162 h, l;
                    split2(v0, v1, h, l);
                    *(__nv_bfloat162*)(Sh + (long)row * MEM_DIM + col) = h;
                    *(__nv_bfloat162*)(Sl + (long)row * MEM_DIM + col) = l;
                } else {
                    *(float2*)(Cmat + (long)row * MEM_DIM + col) = make_float2(v0, v1);
                }
            }
        }
    }
}

// ---------------------------------------------------------------------------
// Combine (warp-per-child for C==8; generic fallback). Writes fp32 states and
// bf16 split copies (A operand for upper-level P-GEMMs).
// ---------------------------------------------------------------------------
__global__ __launch_bounds__(256)
void rcnn_combine(int lo,
                  const int*   __restrict__ cidx,
                  const int*   __restrict__ cdep,
                  const int*   __restrict__ counts,
                  const float* __restrict__ X,
                  const float* __restrict__ D,
                  const float* __restrict__ P,
                  float*       __restrict__ S,
                  __nv_bfloat16* __restrict__ Sh,
                  __nv_bfloat16* __restrict__ Sl) {
    const int i   = lo + (int)blockIdx.x;
    const int tid = threadIdx.x;
    const int cnt = counts[i];

    __shared__ float r[MAX_CH * MEM_DIM];

    if (cnt == 8) {
        const int w = tid >> 5;
        const int l = tid & 31;
        const int g = l * 8;

        const int c  = cidx[i * MAX_CH + w];
        const int dv = cdep[i * MAX_CH + w];

        const float4 x0 = *(const float4*)(X + (long)i  * MEM_DIM + g);
        const float4 x1 = *(const float4*)(X + (long)i  * MEM_DIM + g + 4);
        const float4 d0 = *(const float4*)(D + (long)dv * MEM_DIM + g);
        const float4 d1 = *(const float4*)(D + (long)dv * MEM_DIM + g + 4);
        const float4 p0 = *(const float4*)(P + (long)c  * MEM_DIM + g);
        const float4 p1 = *(const float4*)(P + (long)c  * MEM_DIM + g + 4);

        float m = tanhf(x0.x + d0.x + p0.x);
        m = fmaxf(m, tanhf(x0.y + d0.y + p0.y));
        m = fmaxf(m, tanhf(x0.z + d0.z + p0.z));
        m = fmaxf(m, tanhf(x0.w + d0.w + p0.w));
        m = fmaxf(m, tanhf(x1.x + d1.x + p1.x));
        m = fmaxf(m, tanhf(x1.y + d1.y + p1.y));
        m = fmaxf(m, tanhf(x1.z + d1.z + p1.z));
        m = fmaxf(m, tanhf(x1.w + d1.w + p1.w));

        const long o = (long)i * MEM_DIM + w * 32 + l;
        S[o] = m;
        __nv_bfloat16 h = __float2bfloat16(m);
        Sh[o] = h;
        Sl[o] = __float2bfloat16(m - __bfloat162float(h));
        return;
    }

    const int f = tid;
    const float x = X[(long)i * MEM_DIM + f];
    const long o = (long)i * MEM_DIM + f;

    if (cnt == 0) {
        float v = tanhf(x);
        S[o] = v;
        __nv_bfloat16 h = __float2bfloat16(v);
        Sh[o] = h;
        Sl[o] = __float2bfloat16(v - __bfloat162float(h));
        return;
    }
    const int C = cnt;

    for (int k = 0; k < C; ++k) {
        int c  = cidx[i * MAX_CH + k];
        int dv = cdep[i * MAX_CH + k];
        r[k * MEM_DIM + f] = tanhf(x + D[dv * MEM_DIM + f] + P[(long)c * MEM_DIM + f]);
    }
    __syncthreads();

    float mx = -3.402823466e38f;
    for (int t = 0; t < C; ++t) {
        int j = f * C + t;
        mx = fmaxf(mx, r[(j >> 8) * MEM_DIM + (j & 255)]);
    }
    S[o] = mx;
    __nv_bfloat16 h = __float2bfloat16(mx);
    Sh[o] = h;
    Sl[o] = __float2bfloat16(mx - __bfloat162float(h));
}

// ---------------------------------------------------------------------------
extern "C" void kernel_launch(void* const* d_in, const int* in_sizes, int n_in,
                              void* d_out, int out_size) {
    const float* inputs    = (const float*)d_in[0];
    const float* W         = (const float*)d_in[1];
    const float* bvec      = (const float*)d_in[2];
    const float* deprel    = (const float*)d_in[3];
    const int*   child_idx = (const int*)  d_in[4];
    const int*   child_dep = (const int*)  d_in[5];
    const int*   counts    = (const int*)  d_in[6];
    float*       states    = (float*)d_out;

    float *X = 0, *P = 0, *D = 0;
    __nv_bfloat16 *Wh = 0, *Wl = 0, *Sh = 0, *Sl = 0, *Ih = 0, *Il = 0, *Eh = 0, *El = 0;
    cudaGetSymbolAddress((void**)&X,  g_X);
    cudaGetSymbolAddress((void**)&P,  g_P);
    cudaGetSymbolAddress((void**)&D,  g_D);
    cudaGetSymbolAddress((void**)&Wh, g_Wh);
    cudaGetSymbolAddress((void**)&Wl, g_Wl);
    cudaGetSymbolAddress((void**)&Sh, g_Sh);
    cudaGetSymbolAddress((void**)&Sl, g_Sl);
    cudaGetSymbolAddress((void**)&Ih, g_Ih);
    cudaGetSymbolAddress((void**)&Il, g_Il);
    cudaGetSymbolAddress((void**)&Eh, g_Eh);
    cudaGetSymbolAddress((void**)&El, g_El);

    const int N = in_sizes[0] / IN_DIM;               // 16384
    const int first_leaf = (N + MAX_CH - 2) / MAX_CH; // 2048
    const int SMEM = NSTAGE * ST_BYTES;               // 73728 B

    static bool attr_done = false;
    if (!attr_done) {
        cudaFuncSetAttribute(rcnn_gemm_mma<true, true>,
                             cudaFuncAttributeMaxDynamicSharedMemorySize, SMEM);
        cudaFuncSetAttribute(rcnn_gemm_mma<false, false>,
                             cudaFuncAttributeMaxDynamicSharedMemorySize, SMEM);
        attr_done = true;
    }

    // Phase -1: split all fp32 operands into bf16 hi/lo once.
    split_f32<<<(MEM_DIM * 1024 / 4 + 255) / 256, 256>>>(W, Wh, Wl, MEM_DIM * 1024 / 4);
    split_f32<<<((N * IN_DIM / 4) + 255) / 256, 256>>>(inputs, Ih, Il, N * IN_DIM / 4);
    split_f32<<<(VOCAB * MEM_DIM / 4 + 255) / 256, 256>>>(deprel, Eh, El, VOCAB * MEM_DIM / 4);

    // Phase 0: input projection + bias; leaf rows tanh'd + split in epilogue.
    rcnn_gemm_mma<true, true><<<dim3((unsigned)((N + 63) / 64), 2), 256, SMEM>>>(
        Ih, Il, IN_DIM, Wh, Wl, 0, bvec, X, N, IN_DIM, states, Sh, Sl, first_leaf);
    // deprel projection (tiny)
    rcnn_gemm_mma<false, false><<<dim3(1, 2), 256, SMEM>>>(
        Eh, El, MEM_DIM, Wh, Wl, IN_DIM, 0, D, VOCAB, MEM_DIM, 0, 0, 0, 0);

    // Level starts: s[L] = (8^L - 1)/7
    long s[12];
    s[0] = 0;
    int nl = 0;
    while (s[nl] < N) { s[nl + 1] = 8 * s[nl] + 1; nl++; }

    for (int L = nl - 1; L >= 0; --L) {
        long lo = s[L];
        long hi = s[L + 1] - 1;
        if (hi > first_leaf - 1) hi = first_leaf - 1;
        if (lo > hi) continue;

        long clo = 8 * lo + 1;
        long chi = 8 * hi + 8;
        if (chi > N - 1) chi = N - 1;
        int Mc = (int)(chi - clo + 1);

        rcnn_gemm_mma<false, false><<<dim3((unsigned)((Mc + 63) / 64), 2), 256, SMEM>>>(
            Sh + clo * MEM_DIM, Sl + clo * MEM_DIM, MEM_DIM,
            Wh, Wl, IN_DIM + MEM_DIM, 0, P + clo * MEM_DIM, Mc, MEM_DIM, 0, 0, 0, 0);

        rcnn_combine<<<(unsigned)(hi - lo + 1), 256>>>(
            (int)lo, child_idx, child_dep, counts, X, D, P, states, Sh, Sl);
    }
}

// round 13
// speedup vs baseline: 1.1011x; 1.0225x over previous
#include <cuda_runtime.h>
#include <cuda_bf16.h>
#include <stdint.h>
#include <math.h>

#define N_NODES_MAX 16384
#define IN_DIM 512
#define MEM_DIM 256
#define VOCAB 64
#define MAX_CH 8

// Scratch (allocation-free rule: __device__ globals)
__device__ float g_X[N_NODES_MAX * MEM_DIM];
__device__ float g_P[N_NODES_MAX * MEM_DIM];
__device__ float g_D[VOCAB * MEM_DIM];
__device__ __nv_bfloat16 g_Wh[MEM_DIM * 1024];
__device__ __nv_bfloat16 g_Wl[MEM_DIM * 1024];
__device__ __nv_bfloat16 g_Sh[N_NODES_MAX * MEM_DIM];
__device__ __nv_bfloat16 g_Sl[N_NODES_MAX * MEM_DIM];
__device__ __nv_bfloat16 g_Ih[N_NODES_MAX * IN_DIM];
__device__ __nv_bfloat16 g_Il[N_NODES_MAX * IN_DIM];
__device__ __nv_bfloat16 g_Eh[VOCAB * MEM_DIM];
__device__ __nv_bfloat16 g_El[VOCAB * MEM_DIM];

#define AROW 24              // bf16 per smem row: 16 data + 8 pad (48B)
#define NSTAGE 3
// per-stage byte offsets inside one stage block
#define ST_AH 0
#define ST_AL 3072           // 64*24*2
#define ST_BH 6144
#define ST_BL 12288
#define ST_BYTES 18432

__device__ __forceinline__ void ldsm4(unsigned& r0, unsigned& r1,
                                      unsigned& r2, unsigned& r3, unsigned addr) {
    asm volatile("ldmatrix.sync.aligned.m8n8.x4.shared.b16 {%0,%1,%2,%3}, [%4];"
                 : "=r"(r0), "=r"(r1), "=r"(r2), "=r"(r3) : "r"(addr));
}

__device__ __forceinline__ void mma16816(float* c,
                                         unsigned a0, unsigned a1, unsigned a2, unsigned a3,
                                         unsigned b0, unsigned b1) {
    asm volatile(
        "mma.sync.aligned.m16n8k16.row.col.f32.bf16.bf16.f32 "
        "{%0,%1,%2,%3}, {%4,%5,%6,%7}, {%8,%9}, {%0,%1,%2,%3};"
        : "+f"(c[0]), "+f"(c[1]), "+f"(c[2]), "+f"(c[3])
        : "r"(a0), "r"(a1), "r"(a2), "r"(a3), "r"(b0), "r"(b1));
}

__device__ __forceinline__ void cp16(unsigned saddr, const void* gptr, unsigned src_bytes) {
    asm volatile("cp.async.cg.shared.global [%0], [%1], 16, %2;"
                 :: "r"(saddr), "l"(gptr), "r"(src_bytes));
}
__device__ __forceinline__ void cp_commit() {
    asm volatile("cp.async.commit_group;");
}
template<int N>
__device__ __forceinline__ void cp_wait() {
    asm volatile("cp.async.wait_group %0;" :: "n"(N));
}

__device__ __forceinline__ void split2(float x, float y,
                                       __nv_bfloat162& hi, __nv_bfloat162& lo) {
    __nv_bfloat16 hx = __float2bfloat16(x);
    __nv_bfloat16 hy = __float2bfloat16(y);
    hi = __halves2bfloat162(hx, hy);
    lo = __halves2bfloat162(__float2bfloat16(x - __bfloat162float(hx)),
                            __float2bfloat16(y - __bfloat162float(hy)));
}

// generic fp32 -> bf16 hi/lo split, 4 elems per thread
__global__ __launch_bounds__(256)
void split_f32(const float* __restrict__ src,
               __nv_bfloat16* __restrict__ h, __nv_bfloat16* __restrict__ l, int n4) {
    int i = blockIdx.x * 256 + threadIdx.x;
    if (i >= n4) return;
    float4 v = *(const float4*)(src + (long)i * 4);
    __nv_bfloat162 a, b;
    split2(v.x, v.y, a, b);
    ((__nv_bfloat162*)(h + (long)i * 4))[0] = a;
    ((__nv_bfloat162*)(l + (long)i * 4))[0] = b;
    split2(v.z, v.w, a, b);
    ((__nv_bfloat162*)(h + (long)i * 4))[1] = a;
    ((__nv_bfloat162*)(l + (long)i * 4))[1] = b;
}

// ---------------------------------------------------------------------------
// C[m,n] = sum_k A[m,k] * W[n, wofs+k] (+ bias[n]); A,W pre-split bf16 hi/lo.
// 3-pass split-bf16 tensor GEMM, 3-stage cp.async pipeline, one sync/iter,
// passes de-interleaved so same-accumulator MMAs are 8 apart (no RAW stalls).
// Block 64(M) x 128(N), BK=16, 8 warps (2M x 4N), warp tile 32x32, 3 CTAs/SM.
// ---------------------------------------------------------------------------
template<bool HAS_BIAS, bool LEAF_TANH>
__global__ __launch_bounds__(256, 3)
void rcnn_gemm_mma(const __nv_bfloat16* __restrict__ Agh,
                   const __nv_bfloat16* __restrict__ Agl, int lda,
                   const __nv_bfloat16* __restrict__ Wh,
                   const __nv_bfloat16* __restrict__ Wl, int wofs,
                   const float* __restrict__ bias,
                   float* __restrict__ Cmat, int M, int K,
                   float* __restrict__ S,
                   __nv_bfloat16* __restrict__ Sh,
                   __nv_bfloat16* __restrict__ Sl, int first_leaf) {
    extern __shared__ char smem[];

    const int tid  = threadIdx.x;
    const int lane = tid & 31;
    const int warp = tid >> 5;
    const int wm   = warp >> 2;
    const int wn   = warp & 3;
    const int bm   = blockIdx.x * 64;
    const int bn   = blockIdx.y * 128;

    const int a_r = (tid & 127) >> 1;
    const int a_c = (tid & 1) * 8;
    const bool a_lo = (tid >= 128);
    const int b_r = tid >> 1;
    const int b_c = (tid & 1) * 8;

    const int a_gr = bm + a_r;
    const unsigned a_sz = (a_gr < M) ? 16u : 0u;
    const long a_base = (long)((a_gr < M) ? a_gr : (M - 1)) * lda;
    const __nv_bfloat16* Asrc = a_lo ? Agl : Agh;
    const long b_base = (long)(bn + b_r) * 1024 + wofs;

    unsigned smem_u = (unsigned)__cvta_generic_to_shared(smem);
    unsigned sa_t[NSTAGE], sbh_t[NSTAGE], sbl_t[NSTAGE];
    #pragma unroll
    for (int s = 0; s < NSTAGE; ++s) {
        unsigned base = smem_u + s * ST_BYTES;
        sa_t[s]  = base + (a_lo ? ST_AL : ST_AH) + (unsigned)(a_r * AROW + a_c) * 2u;
        sbh_t[s] = base + ST_BH + (unsigned)(b_r * AROW + b_c) * 2u;
        sbl_t[s] = base + ST_BL + (unsigned)(b_r * AROW + b_c) * 2u;
    }

    const int ntile = K >> 4;

    auto stage_of = [](int t) { return t % NSTAGE; };
    auto issue = [&](int t) {
        const int s = stage_of(t);
        const int kof = t * 16;
        cp16(sa_t[s],  Asrc + a_base + kof + a_c, a_sz);
        cp16(sbh_t[s], Wh + b_base + kof + b_c, 16u);
        cp16(sbl_t[s], Wl + b_base + kof + b_c, 16u);
    };

    float acc[2][4][4];
    #pragma unroll
    for (int i = 0; i < 2; ++i) {
        #pragma unroll
        for (int j = 0; j < 4; ++j) {
            #pragma unroll
            for (int q = 0; q < 4; ++q) { acc[i][j][q] = 0.f; }
        }
    }

    // prologue: tiles 0..NSTAGE-2, one committed group each
    #pragma unroll
    for (int s = 0; s < NSTAGE - 1; ++s) {
        if (s < ntile) issue(s);
        cp_commit();
    }

    const int gq8 = lane >> 3;
    const int wi  = lane & 7;
    const int a_row = wm * 32 + wi + 8 * (gq8 & 1);
    const int a_kh  = (gq8 >> 1) * 8;
    const int b_row = wn * 32 + wi + 8 * (gq8 >> 1);
    const int b_kh  = (gq8 & 1) * 8;

    for (int it = 0; it < ntile; ++it) {
        cp_wait<NSTAGE - 2>();
        __syncthreads();

        if (it + NSTAGE - 1 < ntile) issue(it + NSTAGE - 1);
        cp_commit();

        const unsigned sbase = smem_u + (unsigned)stage_of(it) * ST_BYTES;

        unsigned Ahf[2][4], Alf[2][4], Bhf[2][4], Blf[2][4];
        #pragma unroll
        for (int mt = 0; mt < 2; ++mt) {
            unsigned off = (unsigned)((a_row + mt * 16) * AROW + a_kh) * 2u;
            ldsm4(Ahf[mt][0], Ahf[mt][1], Ahf[mt][2], Ahf[mt][3], sbase + ST_AH + off);
            ldsm4(Alf[mt][0], Alf[mt][1], Alf[mt][2], Alf[mt][3], sbase + ST_AL + off);
        }
        #pragma unroll
        for (int p = 0; p < 2; ++p) {
            unsigned off = (unsigned)((b_row + p * 16) * AROW + b_kh) * 2u;
            ldsm4(Bhf[p][0], Bhf[p][1], Bhf[p][2], Bhf[p][3], sbase + ST_BH + off);
            ldsm4(Blf[p][0], Blf[p][1], Blf[p][2], Blf[p][3], sbase + ST_BL + off);
        }

        // pass 1: hi*hi (8 independent accumulators back-to-back)
        #pragma unroll
        for (int mt = 0; mt < 2; ++mt)
            #pragma unroll
            for (int p = 0; p < 2; ++p)
                #pragma unroll
                for (int nh = 0; nh < 2; ++nh)
                    mma16816(acc[mt][p * 2 + nh],
                             Ahf[mt][0], Ahf[mt][1], Ahf[mt][2], Ahf[mt][3],
                             Bhf[p][2 * nh], Bhf[p][2 * nh + 1]);
        // pass 2: hi*lo
        #pragma unroll
        for (int mt = 0; mt < 2; ++mt)
            #pragma unroll
            for (int p = 0; p < 2; ++p)
                #pragma unroll
                for (int nh = 0; nh < 2; ++nh)
                    mma16816(acc[mt][p * 2 + nh],
                             Ahf[mt][0], Ahf[mt][1], Ahf[mt][2], Ahf[mt][3],
                             Blf[p][2 * nh], Blf[p][2 * nh + 1]);
        // pass 3: lo*hi
        #pragma unroll
        for (int mt = 0; mt < 2; ++mt)
            #pragma unroll
            for (int p = 0; p < 2; ++p)
                #pragma unroll
                for (int nh = 0; nh < 2; ++nh)
                    mma16816(acc[mt][p * 2 + nh],
                             Alf[mt][0], Alf[mt][1], Alf[mt][2], Alf[mt][3],
                             Bhf[p][2 * nh], Bhf[p][2 * nh + 1]);
    }

    // epilogue
    const int gq  = lane >> 2;
    const int tig = lane & 3;
    #pragma unroll
    for (int mt = 0; mt < 2; ++mt) {
        #pragma unroll
        for (int rh = 0; rh < 2; ++rh) {
            const int row = bm + wm * 32 + mt * 16 + rh * 8 + gq;
            if (row >= M) continue;
            const bool leaf = LEAF_TANH && (row >= first_leaf);
            #pragma unroll
            for (int nt = 0; nt < 4; ++nt) {
                const int col = bn + wn * 32 + nt * 8 + 2 * tig;
                float v0 = acc[mt][nt][2 * rh + 0];
                float v1 = acc[mt][nt][2 * rh + 1];
                if (HAS_BIAS) { v0 += bias[col]; v1 += bias[col + 1]; }
                if (leaf) {
                    v0 = tanhf(v0); v1 = tanhf(v1);
                    *(float2*)(S + (long)row * MEM_DIM + col) = make_float2(v0, v1);
                    __nv_bfloat162 h, l;
                    split2(v0, v1, h, l);
                    *(__nv_bfloat162*)(Sh + (long)row * MEM_DIM + col) = h;
                    *(__nv_bfloat162*)(Sl + (long)row * MEM_DIM + col) = l;
                } else {
                    *(float2*)(Cmat + (long)row * MEM_DIM + col) = make_float2(v0, v1);
                }
            }
        }
    }
}

// ---------------------------------------------------------------------------
// Combine (warp-per-child for C==8; generic fallback). Writes fp32 states and
// bf16 split copies (A operand for upper-level P-GEMMs).
// ---------------------------------------------------------------------------
__global__ __launch_bounds__(256)
void rcnn_combine(int lo,
                  const int*   __restrict__ cidx,
                  const int*   __restrict__ cdep,
                  const int*   __restrict__ counts,
                  const float* __restrict__ X,
                  const float* __restrict__ D,
                  const float* __restrict__ P,
                  float*       __restrict__ S,
                  __nv_bfloat16* __restrict__ Sh,
                  __nv_bfloat16* __restrict__ Sl) {
    const int i   = lo + (int)blockIdx.x;
    const int tid = threadIdx.x;
    const int cnt = counts[i];

    __shared__ float r[MAX_CH * MEM_DIM];

    if (cnt == 8) {
        const int w = tid >> 5;
        const int l = tid & 31;
        const int g = l * 8;

        const int c  = cidx[i * MAX_CH + w];
        const int dv = cdep[i * MAX_CH + w];

        const float4 x0 = *(const float4*)(X + (long)i  * MEM_DIM + g);
        const float4 x1 = *(const float4*)(X + (long)i  * MEM_DIM + g + 4);
        const float4 d0 = *(const float4*)(D + (long)dv * MEM_DIM + g);
        const float4 d1 = *(const float4*)(D + (long)dv * MEM_DIM + g + 4);
        const float4 p0 = *(const float4*)(P + (long)c  * MEM_DIM + g);
        const float4 p1 = *(const float4*)(P + (long)c  * MEM_DIM + g + 4);

        float m = tanhf(x0.x + d0.x + p0.x);
        m = fmaxf(m, tanhf(x0.y + d0.y + p0.y));
        m = fmaxf(m, tanhf(x0.z + d0.z + p0.z));
        m = fmaxf(m, tanhf(x0.w + d0.w + p0.w));
        m = fmaxf(m, tanhf(x1.x + d1.x + p1.x));
        m = fmaxf(m, tanhf(x1.y + d1.y + p1.y));
        m = fmaxf(m, tanhf(x1.z + d1.z + p1.z));
        m = fmaxf(m, tanhf(x1.w + d1.w + p1.w));

        const long o = (long)i * MEM_DIM + w * 32 + l;
        S[o] = m;
        __nv_bfloat16 h = __float2bfloat16(m);
        Sh[o] = h;
        Sl[o] = __float2bfloat16(m - __bfloat162float(h));
        return;
    }

    const int f = tid;
    const float x = X[(long)i * MEM_DIM + f];
    const long o = (long)i * MEM_DIM + f;

    if (cnt == 0) {
        float v = tanhf(x);
        S[o] = v;
        __nv_bfloat16 h = __float2bfloat16(v);
        Sh[o] = h;
        Sl[o] = __float2bfloat16(v - __bfloat162float(h));
        return;
    }
    const int C = cnt;

    for (int k = 0; k < C; ++k) {
        int c  = cidx[i * MAX_CH + k];
        int dv = cdep[i * MAX_CH + k];
        r[k * MEM_DIM + f] = tanhf(x + D[dv * MEM_DIM + f] + P[(long)c * MEM_DIM + f]);
    }
    __syncthreads();

    float mx = -3.402823466e38f;
    for (int t = 0; t < C; ++t) {
        int j = f * C + t;
        mx = fmaxf(mx, r[(j >> 8) * MEM_DIM + (j & 255)]);
    }
    S[o] = mx;
    __nv_bfloat16 h = __float2bfloat16(mx);
    Sh[o] = h;
    Sl[o] = __float2bfloat16(mx - __bfloat162float(h));
}

// ---------------------------------------------------------------------------
extern "C" void kernel_launch(void* const* d_in, const int* in_sizes, int n_in,
                              void* d_out, int out_size) {
    const float* inputs    = (const float*)d_in[0];
    const float* W         = (const float*)d_in[1];
    const float* bvec      = (const float*)d_in[2];
    const float* deprel    = (const float*)d_in[3];
    const int*   child_idx = (const int*)  d_in[4];
    const int*   child_dep = (const int*)  d_in[5];
    const int*   counts    = (const int*)  d_in[6];
    float*       states    = (float*)d_out;

    float *X = 0, *P = 0, *D = 0;
    __nv_bfloat16 *Wh = 0, *Wl = 0, *Sh = 0, *Sl = 0, *Ih = 0, *Il = 0, *Eh = 0, *El = 0;
    cudaGetSymbolAddress((void**)&X,  g_X);
    cudaGetSymbolAddress((void**)&P,  g_P);
    cudaGetSymbolAddress((void**)&D,  g_D);
    cudaGetSymbolAddress((void**)&Wh, g_Wh);
    cudaGetSymbolAddress((void**)&Wl, g_Wl);
    cudaGetSymbolAddress((void**)&Sh, g_Sh);
    cudaGetSymbolAddress((void**)&Sl, g_Sl);
    cudaGetSymbolAddress((void**)&Ih, g_Ih);
    cudaGetSymbolAddress((void**)&Il, g_Il);
    cudaGetSymbolAddress((void**)&Eh, g_Eh);
    cudaGetSymbolAddress((void**)&El, g_El);

    const int N = in_sizes[0] / IN_DIM;               // 16384
    const int first_leaf = (N + MAX_CH - 2) / MAX_CH; // 2048
    const int SMEM = NSTAGE * ST_BYTES;               // 55296 B

    static bool attr_done = false;
    if (!attr_done) {
        cudaFuncSetAttribute(rcnn_gemm_mma<true, true>,
                             cudaFuncAttributeMaxDynamicSharedMemorySize, SMEM);
        cudaFuncSetAttribute(rcnn_gemm_mma<false, false>,
                             cudaFuncAttributeMaxDynamicSharedMemorySize, SMEM);
        attr_done = true;
    }

    // Phase -1: split all fp32 operands into bf16 hi/lo once.
    split_f32<<<(MEM_DIM * 1024 / 4 + 255) / 256, 256>>>(W, Wh, Wl, MEM_DIM * 1024 / 4);
    split_f32<<<((N * IN_DIM / 4) + 255) / 256, 256>>>(inputs, Ih, Il, N * IN_DIM / 4);
    split_f32<<<(VOCAB * MEM_DIM / 4 + 255) / 256, 256>>>(deprel, Eh, El, VOCAB * MEM_DIM / 4);

    // Phase 0: input projection + bias; leaf rows tanh'd + split in epilogue.
    rcnn_gemm_mma<true, true><<<dim3((unsigned)((N + 63) / 64), 2), 256, SMEM>>>(
        Ih, Il, IN_DIM, Wh, Wl, 0, bvec, X, N, IN_DIM, states, Sh, Sl, first_leaf);
    // deprel projection (tiny)
    rcnn_gemm_mma<false, false><<<dim3(1, 2), 256, SMEM>>>(
        Eh, El, MEM_DIM, Wh, Wl, IN_DIM, 0, D, VOCAB, MEM_DIM, 0, 0, 0, 0);

    // Level starts: s[L] = (8^L - 1)/7
    long s[12];
    s[0] = 0;
    int nl = 0;
    while (s[nl] < N) { s[nl + 1] = 8 * s[nl] + 1; nl++; }

    for (int L = nl - 1; L >= 0; --L) {
        long lo = s[L];
        long hi = s[L + 1] - 1;
        if (hi > first_leaf - 1) hi = first_leaf - 1;
        if (lo > hi) continue;

        long clo = 8 * lo + 1;
        long chi = 8 * hi + 8;
        if (chi > N - 1) chi = N - 1;
        int Mc = (int)(chi - clo + 1);

        rcnn_gemm_mma<false, false><<<dim3((unsigned)((Mc + 63) / 64), 2), 256, SMEM>>>(
            Sh + clo * MEM_DIM, Sl + clo * MEM_DIM, MEM_DIM,
            Wh, Wl, IN_DIM + MEM_DIM, 0, P + clo * MEM_DIM, Mc, MEM_DIM, 0, 0, 0, 0);

        rcnn_combine<<<(unsigned)(hi - lo + 1), 256>>>(
            (int)lo, child_idx, child_dep, counts, X, D, P, states, Sh, Sl);
    }
}